// round 14
// baseline (speedup 1.0000x reference)
#include <cuda_runtime.h>
#include <cuda_fp16.h>
#include <cstdint>

// Problem dims
#define BATCH    8192
#define DIM      128          // in_dim == out_dim
#define KTOT     384          // permuted K: k = (half*3+pw)*64 + (j&63)
#define MTILE    64           // batch rows per CTA
#define NTILE    64           // output cols per CTA (N-split 2)
#define THREADS  256          // 8 warps: 4 (m) x 2 (n)
#define NCTA     ((BATCH / MTILE) * 2)   // 256 -> 2 CTAs/SM

// fp16 coefficients (permuted K order): g_Bf[o*384 + c*64 + (j&63)]
__device__ __half g_Bf[DIM * KTOT];
__device__ float g_Bias[DIM];

// smem layout (96 KB per CTA -> 2 CTAs/SM):
//   A: 6 chunks x Af[64][64]f16 8K @ c*8192          = 48 KB @ 0
//   B: 6 chunks x Bf[64][64]f16 8K @ 49152 + c*8192  = 48 KB
#define A_CHUNK_STRIDE 8192u
#define B_BASE         49152u
#define B_CHUNK_STRIDE 8192u
#define SMEM_TOTAL     98304

// ---------------- helpers ----------------
__device__ __forceinline__ uint32_t smem_u32(const void* p) {
    uint32_t a;
    asm("{ .reg .u64 t; cvta.to.shared.u64 t, %1; cvt.u32.u64 %0, t; }" : "=r"(a) : "l"(p));
    return a;
}
__device__ __forceinline__ uint32_t swz128(uint32_t off) { return off ^ ((off >> 3) & 0x70); }

#define CP_ASYNC16(dst_u32, src_ptr)                                              \
    asm volatile("{ .reg .u64 g; cvta.to.global.u64 g, %1;\n"                     \
                 "cp.async.cg.shared.global [%0], [g], 16; }"                     \
                 :: "r"(dst_u32), "l"(src_ptr) : "memory")
#define CP_COMMIT()  asm volatile("cp.async.commit_group;" ::: "memory")
#define CP_WAITG(n)  asm volatile("cp.async.wait_group %0;" :: "n"(n) : "memory")

#define LDSM4(r, addr)                                                            \
    asm volatile("ldmatrix.sync.aligned.m8n8.x4.shared.b16 {%0,%1,%2,%3}, [%4];"  \
                 : "=r"((r)[0]), "=r"((r)[1]), "=r"((r)[2]), "=r"((r)[3])         \
                 : "r"(addr))

#define MMA_F16(c, A, b0v, b1v)                                                   \
    asm volatile("mma.sync.aligned.m16n8k16.row.col.f32.f16.f16.f32 "             \
                 "{%0,%1,%2,%3}, {%4,%5,%6,%7}, {%8,%9}, {%0,%1,%2,%3};"          \
                 : "+f"((c)[0]), "+f"((c)[1]), "+f"((c)[2]), "+f"((c)[3])         \
                 : "r"((A)[0]), "r"((A)[1]), "r"((A)[2]), "r"((A)[3]),            \
                   "r"(b0v), "r"(b1v))

__device__ __forceinline__ uint32_t pack_half2(float a, float b) {
    __half ha = __float2half_rn(a), hb = __float2half_rn(b);
    return (uint32_t)__half_as_ushort(ha) | ((uint32_t)__half_as_ushort(hb) << 16);
}

// ---------------- prologue kernel: coeff -> fp16 (permuted K) + fused bias ----------------
__global__ void prep_kernel(const float* __restrict__ coeff) {
    asm volatile("griddepcontrol.launch_dependents;");

    const int tid = threadIdx.x;
    const int idx = blockIdx.x * 256 + tid;       // edge index [0, 16384)
    const int o = idx >> 7, j = idx & 127;
    float4 cf = reinterpret_cast<const float4*>(coeff)[idx];
    float v[3] = {cf.y, cf.z, cf.w};              // degrees 1..3
    const int cbase = (j >= 64) ? 3 : 0;
#pragma unroll
    for (int pw = 0; pw < 3; ++pw)
        g_Bf[o * KTOT + (cbase + pw) * 64 + (j & 63)] = __float2half_rn(v[pw]);
    float s = cf.x;
#pragma unroll
    for (int off = 16; off; off >>= 1)
        s += __shfl_xor_sync(0xffffffffu, s, off);
    __shared__ float ps[8];
    if ((tid & 31) == 0) ps[tid >> 5] = s;
    __syncthreads();
    if (tid == 0)   g_Bias[o] = ps[0] + ps[1] + ps[2] + ps[3];
    if (tid == 128) g_Bias[o] = ps[4] + ps[5] + ps[6] + ps[7];
}

// ---------------- main kernel ----------------
__global__ void __launch_bounds__(THREADS, 2)
kan_mma(const float* __restrict__ x, float* __restrict__ out) {
    extern __shared__ char smem[];
    const uint32_t sb = smem_u32(smem);
    const int tid  = threadIdx.x;
    const int lane = tid & 31;
    const int wid  = tid >> 5;
    const int b0    = (blockIdx.x >> 1) * MTILE;
    const int nbase = (blockIdx.x & 1) * NTILE;

    // warp tile (16 x 32): 4 m-warps x 2 n-warps
    const int m0 = (wid & 3) * 16;
    const int n0 = (wid >> 2) * 32;

    // ---- 1) FIRST: x loads (longest-latency DRAM dependency) ----
    const int sr = tid >> 2;                      // row 0..63
    const int sq = tid & 3;                       // quarter: 16 j each
    const float4* xr = reinterpret_cast<const float4*>(x + (size_t)(b0 + sr) * DIM);
    float4 xv[8];
#pragma unroll
    for (int q = 0; q < 4; ++q) {
        xv[q]     = xr[sq * 4 + q];               // half 0
        xv[4 + q] = xr[16 + sq * 4 + q];          // half 1
    }

    // ---- 2) build full A tile (prep-independent) ----
    {
        const uint32_t ab0 = swz128((uint32_t)(sr * 128 + sq * 32));
        const uint32_t ab1 = swz128((uint32_t)(sr * 128 + sq * 32 + 16));
#pragma unroll
        for (int h = 0; h < 2; ++h) {
            float xb[16], w[16];
#pragma unroll
            for (int q = 0; q < 4; ++q) {
                float4 v = xv[h * 4 + q];
                xb[4 * q + 0] = v.x; xb[4 * q + 1] = v.y;
                xb[4 * q + 2] = v.z; xb[4 * q + 3] = v.w;
            }
#pragma unroll
            for (int i = 0; i < 16; ++i) w[i] = xb[i];
#pragma unroll
            for (int pw = 0; pw < 3; ++pw) {
                const uint32_t cb = (uint32_t)(h * 3 + pw) * A_CHUNK_STRIDE;
                *reinterpret_cast<uint4*>(smem + cb + ab0) =
                    make_uint4(pack_half2(w[0], w[1]),  pack_half2(w[2], w[3]),
                               pack_half2(w[4], w[5]),  pack_half2(w[6], w[7]));
                *reinterpret_cast<uint4*>(smem + cb + ab1) =
                    make_uint4(pack_half2(w[8], w[9]),  pack_half2(w[10], w[11]),
                               pack_half2(w[12], w[13]), pack_half2(w[14], w[15]));
                if (pw < 2) {
#pragma unroll
                    for (int i = 0; i < 16; ++i) w[i] *= xb[i];
                }
            }
        }
    }

    // ---- 3) wait for prep kernel's writes (g_Bf, g_Bias) ----
    asm volatile("griddepcontrol.wait;" ::: "memory");

    // ---- 4) B cp.async (this CTA's 64-output slice), two commit groups ----
#pragma unroll
    for (int i = 0; i < 6; ++i) {
        int idx = tid + i * THREADS;              // 0..1535 -> chunks 0..2
        int cn = idx >> 9;                        // 512 x16B per chunk
        int n = (idx >> 3) & 63, k8 = idx & 7;
        const __half* src = g_Bf + (size_t)(nbase + n) * KTOT + cn * 64 + k8 * 8;
        uint32_t dst = B_BASE + (uint32_t)cn * B_CHUNK_STRIDE
                     + swz128((uint32_t)(n * 128 + k8 * 16));
        CP_ASYNC16(sb + dst, src);
    }
    CP_COMMIT();
#pragma unroll
    for (int i = 6; i < 12; ++i) {
        int idx = tid + i * THREADS;              // 1536..3071 -> chunks 3..5
        int cn = idx >> 9;
        int n = (idx >> 3) & 63, k8 = idx & 7;
        const __half* src = g_Bf + (size_t)(nbase + n) * KTOT + cn * 64 + k8 * 8;
        uint32_t dst = B_BASE + (uint32_t)cn * B_CHUNK_STRIDE
                     + swz128((uint32_t)(n * 128 + k8 * 16));
        CP_ASYNC16(sb + dst, src);
    }
    CP_COMMIT();

    // bias prefetch
    float2 bs[4];
#pragma unroll
    for (int nj = 0; nj < 4; ++nj)
        bs[nj] = *reinterpret_cast<const float2*>(
            g_Bias + nbase + n0 + nj * 8 + 2 * (lane & 3));

    // ---- 5) mainloop: two phases of 12 k16-steps, 3-set fragment pipeline ----
    float acc[4][4];
#pragma unroll
    for (int nj = 0; nj < 4; ++nj)
#pragma unroll
        for (int i = 0; i < 4; ++i) acc[nj][i] = 0.f;

    const uint32_t a_row = (uint32_t)(m0 + (lane & 15));
    const uint32_t a_kb  = (uint32_t)((lane >> 4) * 16);
    const uint32_t b_row = (uint32_t)(n0 + (lane & 7) + ((lane >> 4) << 3));
    const uint32_t b_kb  = (uint32_t)(((lane >> 3) & 1) * 16);

    uint32_t af[3][4], bf[3][2][4];

    auto load_step = [&](int step, int s) {
        const uint32_t ab = (uint32_t)(step >> 2) * A_CHUNK_STRIDE;
        const uint32_t bb = B_BASE + (uint32_t)(step >> 2) * B_CHUNK_STRIDE;
        const int ks = step & 3;
        LDSM4(af[s], sb + ab + swz128(a_row * 128 + ks * 32 + a_kb));
#pragma unroll
        for (int ni = 0; ni < 2; ++ni) {
            uint32_t off = swz128((b_row + ni * 16) * 128 + ks * 32 + b_kb);
            LDSM4(bf[s][ni], sb + bb + off);
        }
    };
    auto mma_step = [&](int s) {
#pragma unroll
        for (int nj = 0; nj < 4; ++nj) {
            const int ni = nj >> 1, br = (nj & 1) * 2;
            MMA_F16(acc[nj], af[s], bf[s][ni][br], bf[s][ni][br + 1]);
        }
    };

    // phase 0: chunks 0-2 (steps 0..11)
    CP_WAITG(1);
    __syncthreads();
    load_step(0, 0);
    load_step(1, 1);
#pragma unroll
    for (int s = 0; s < 12; ++s) {
        if (s + 2 < 12) load_step(s + 2, (s + 2) % 3);
        mma_step(s % 3);
    }

    // phase 1: chunks 3-5 (steps 12..23)
    CP_WAITG(0);
    __syncthreads();
    load_step(12, 0);
    load_step(13, 1);
#pragma unroll
    for (int s = 0; s < 12; ++s) {
        if (s + 2 < 12) load_step(12 + s + 2, (s + 2) % 3);
        mma_step(s % 3);
    }

    // ---- 6) epilogue: bias + store ----
    const int r0 = b0 + m0 + (lane >> 2);
#pragma unroll
    for (int nj = 0; nj < 4; ++nj) {
        const int col = nbase + n0 + nj * 8 + 2 * (lane & 3);
        float2 v0 = make_float2(acc[nj][0] + bs[nj].x, acc[nj][1] + bs[nj].y);
        float2 v1 = make_float2(acc[nj][2] + bs[nj].x, acc[nj][3] + bs[nj].y);
        *reinterpret_cast<float2*>(out + (size_t)r0 * DIM + col)       = v0;
        *reinterpret_cast<float2*>(out + (size_t)(r0 + 8) * DIM + col) = v1;
    }
}

// ---------------- launch ----------------
extern "C" void kernel_launch(void* const* d_in, const int* in_sizes, int n_in,
                              void* d_out, int out_size) {
    const float* x     = (const float*)d_in[0];   // [8192, 128] fp32
    const float* coeff = (const float*)d_in[1];   // [16384, 4]  fp32
    float* out = (float*)d_out;                   // [8192, 128] fp32

    cudaFuncSetAttribute(kan_mma, cudaFuncAttributeMaxDynamicSharedMemorySize, SMEM_TOTAL);

    prep_kernel<<<64, 256>>>(coeff);

    // PDL: main may start while prep runs; griddepcontrol.wait orders g_Bf reads.
    cudaLaunchConfig_t cfg = {};
    cfg.gridDim  = dim3(NCTA, 1, 1);
    cfg.blockDim = dim3(THREADS, 1, 1);
    cfg.dynamicSmemBytes = SMEM_TOTAL;
    cfg.stream = 0;
    cudaLaunchAttribute attr[1];
    attr[0].id = cudaLaunchAttributeProgrammaticStreamSerialization;
    attr[0].val.programmaticStreamSerializationAllowed = 1;
    cfg.attrs = attr;
    cfg.numAttrs = 1;
    cudaLaunchKernelEx(&cfg, kan_mma, x, out);
}

// round 15
// speedup vs baseline: 1.0201x; 1.0201x over previous
#include <cuda_runtime.h>
#include <cuda_fp16.h>
#include <cstdint>

// Problem dims
#define BATCH    8192
#define DIM      128          // in_dim == out_dim
#define KTOT     384          // permuted K: k = (half*3+pw)*64 + (j&63)
#define MTILE    128          // batch rows per CTA
#define NTILE    64           // output cols per CTA
#define THREADS  512          // 16 warps: 8 (m) x 2 (n)
#define NCTA     128          // 64 M-tiles x 2 N-halves, one full wave

// smem (145 KB, 1 CTA/SM):
//   A: 6 chunks x Af[128][64]f16 16K @ c*16384 = 96 KB @ 0
//   B: 6 chunks x Bf[64][64]f16  8K @ 98304 + c*8192 = 48 KB
//   bias partials: 64 o x 2 slots x f32 = 512 B @ 147456
#define A_CHUNK   16384u
#define B_BASE    98304u
#define B_CHUNK   8192u
#define BIAS_OFF  147456u
#define SMEM_TOTAL 148480

// ---------------- helpers ----------------
__device__ __forceinline__ uint32_t smem_u32(const void* p) {
    uint32_t a;
    asm("{ .reg .u64 t; cvta.to.shared.u64 t, %1; cvt.u32.u64 %0, t; }" : "=r"(a) : "l"(p));
    return a;
}
__device__ __forceinline__ uint32_t swz128(uint32_t off) { return off ^ ((off >> 3) & 0x70); }

#define LDSM4(r, addr)                                                            \
    asm volatile("ldmatrix.sync.aligned.m8n8.x4.shared.b16 {%0,%1,%2,%3}, [%4];"  \
                 : "=r"((r)[0]), "=r"((r)[1]), "=r"((r)[2]), "=r"((r)[3])         \
                 : "r"(addr))

#define MMA_F16(c, A, b0v, b1v)                                                   \
    asm volatile("mma.sync.aligned.m16n8k16.row.col.f32.f16.f16.f32 "             \
                 "{%0,%1,%2,%3}, {%4,%5,%6,%7}, {%8,%9}, {%0,%1,%2,%3};"          \
                 : "+f"((c)[0]), "+f"((c)[1]), "+f"((c)[2]), "+f"((c)[3])         \
                 : "r"((A)[0]), "r"((A)[1]), "r"((A)[2]), "r"((A)[3]),            \
                   "r"(b0v), "r"(b1v))

__device__ __forceinline__ uint32_t pack_half2(float a, float b) {
    __half2 h = __floats2half2_rn(a, b);
    return *reinterpret_cast<uint32_t*>(&h);
}

// ---------------- single fused kernel ----------------
__global__ void __launch_bounds__(THREADS, 1)
kan_fused(const float* __restrict__ x, const float* __restrict__ coeff,
          float* __restrict__ out) {
    extern __shared__ char smem[];
    const uint32_t sb = smem_u32(smem);
    const int tid  = threadIdx.x;
    const int lane = tid & 31;
    const int wid  = tid >> 5;
    const int b0    = (blockIdx.x >> 1) * MTILE;
    const int nbase = (blockIdx.x & 1) * NTILE;

    // warp tile (16 x 32): 8 m-warps x 2 n-warps
    const int m0 = (wid & 7) * 16;
    const int n0 = (wid >> 3) * 32;

    // ---- 1) issue x loads first (DRAM latency pole) ----
    // A staging: thread = row sr (0..127) x quarter sq (0..3); covers
    // j in [h*64 + sq*16, +16) for both halves h.
    const int sr = tid >> 2;
    const int sq = tid & 3;
    const float4* xr = reinterpret_cast<const float4*>(x + (size_t)(b0 + sr) * DIM);
    float4 xv[8];
#pragma unroll
    for (int h = 0; h < 2; ++h)
#pragma unroll
        for (int q = 0; q < 4; ++q)
            xv[h * 4 + q] = xr[h * 16 + sq * 4 + q];

    // ---- 2) convert this CTA's coeff slice -> fp16 B smem + bias partials ----
    // local edge el = oo*128 + j, oo in [0,64). Thread handles pairs
    // el = 2*tid + p*1024, p = 0..7 (2 edges per pair, 16 edges total).
    // For fixed p, a warp covers 64 consecutive el => one oo, one j-half.
    {
        const float4* cb = reinterpret_cast<const float4*>(coeff)
                         + (size_t)nbase * 128;
#pragma unroll
        for (int batch = 0; batch < 2; ++batch) {
            float4 cf[8];
#pragma unroll
            for (int pp = 0; pp < 4; ++pp) {
                int el = 2 * tid + (batch * 4 + pp) * 1024;
                cf[2 * pp]     = cb[el];
                cf[2 * pp + 1] = cb[el + 1];
            }
#pragma unroll
            for (int pp = 0; pp < 4; ++pp) {
                int p  = batch * 4 + pp;
                int el = 2 * tid + p * 1024;
                int oo = el >> 7;
                int j  = el & 127;
                int h  = j >> 6;
                float4 c0 = cf[2 * pp], c1 = cf[2 * pp + 1];

                const uint32_t rowoff = swz128((uint32_t)(oo * 128 + (j & 63) * 2));
                *reinterpret_cast<uint32_t*>(
                    smem + B_BASE + (h * 3 + 0) * B_CHUNK + rowoff) = pack_half2(c0.y, c1.y);
                *reinterpret_cast<uint32_t*>(
                    smem + B_BASE + (h * 3 + 1) * B_CHUNK + rowoff) = pack_half2(c0.z, c1.z);
                *reinterpret_cast<uint32_t*>(
                    smem + B_BASE + (h * 3 + 2) * B_CHUNK + rowoff) = pack_half2(c0.w, c1.w);

                // bias partial: whole warp shares oo; reduce and store to unique slot
                float s = c0.x + c1.x;
#pragma unroll
                for (int off = 16; off; off >>= 1)
                    s += __shfl_xor_sync(0xffffffffu, s, off);
                if (lane == 0)
                    reinterpret_cast<float*>(smem + BIAS_OFF)[oo * 2 + (wid & 1)] = s;
            }
        }
    }

    // ---- 3) build full A tile (x arrived during conversion) ----
    {
        const uint32_t a0 = swz128((uint32_t)(sr * 128 + sq * 32));
        const uint32_t a1 = swz128((uint32_t)(sr * 128 + sq * 32 + 16));
#pragma unroll
        for (int h = 0; h < 2; ++h) {
            float xb[16], w[16];
#pragma unroll
            for (int q = 0; q < 4; ++q) {
                float4 v = xv[h * 4 + q];
                xb[4 * q + 0] = v.x; xb[4 * q + 1] = v.y;
                xb[4 * q + 2] = v.z; xb[4 * q + 3] = v.w;
            }
#pragma unroll
            for (int i = 0; i < 16; ++i) w[i] = xb[i];
#pragma unroll
            for (int pw = 0; pw < 3; ++pw) {
                const uint32_t cbk = (uint32_t)(h * 3 + pw) * A_CHUNK;
                *reinterpret_cast<uint4*>(smem + cbk + a0) =
                    make_uint4(pack_half2(w[0], w[1]),   pack_half2(w[2], w[3]),
                               pack_half2(w[4], w[5]),   pack_half2(w[6], w[7]));
                *reinterpret_cast<uint4*>(smem + cbk + a1) =
                    make_uint4(pack_half2(w[8], w[9]),   pack_half2(w[10], w[11]),
                               pack_half2(w[12], w[13]), pack_half2(w[14], w[15]));
                if (pw < 2) {
#pragma unroll
                    for (int i = 0; i < 16; ++i) w[i] *= xb[i];
                }
            }
        }
    }

    // ---- 4) single synchronization point ----
    __syncthreads();

    // ---- 5) 24-step mainloop, 3-set fragment pipeline (lookahead 2) ----
    float acc[4][4];
#pragma unroll
    for (int nj = 0; nj < 4; ++nj)
#pragma unroll
        for (int i = 0; i < 4; ++i) acc[nj][i] = 0.f;

    const uint32_t a_row = (uint32_t)(m0 + (lane & 15));
    const uint32_t a_kb  = (uint32_t)((lane >> 4) * 16);
    const uint32_t b_row = (uint32_t)(n0 + (lane & 7) + ((lane >> 4) << 3));
    const uint32_t b_kb  = (uint32_t)(((lane >> 3) & 1) * 16);

    uint32_t af[3][4], bf[3][2][4];

    auto load_step = [&](int step, int s) {
        const uint32_t ab = (uint32_t)(step >> 2) * A_CHUNK;
        const uint32_t bb = B_BASE + (uint32_t)(step >> 2) * B_CHUNK;
        const int ks = step & 3;
        LDSM4(af[s], sb + ab + swz128(a_row * 128 + ks * 32 + a_kb));
#pragma unroll
        for (int ni = 0; ni < 2; ++ni) {
            uint32_t off = swz128((b_row + ni * 16) * 128 + ks * 32 + b_kb);
            LDSM4(bf[s][ni], sb + bb + off);
        }
    };
    auto mma_step = [&](int s) {
#pragma unroll
        for (int nj = 0; nj < 4; ++nj) {
            const int ni = nj >> 1, br = (nj & 1) * 2;
            MMA_F16(acc[nj], af[s], bf[s][ni][br], bf[s][ni][br + 1]);
        }
    };

    load_step(0, 0);
    load_step(1, 1);
#pragma unroll
    for (int step = 0; step < 24; ++step) {
        if (step + 2 < 24) load_step(step + 2, (step + 2) % 3);
        mma_step(step % 3);
    }

    // ---- 6) epilogue: bias (sum of 2 partials) + store ----
    const float* bp = reinterpret_cast<const float*>(smem + BIAS_OFF);
    const int r0 = b0 + m0 + (lane >> 2);
#pragma unroll
    for (int nj = 0; nj < 4; ++nj) {
        const int cl = n0 + nj * 8 + 2 * (lane & 3);        // local col, even
        float4 bb = *reinterpret_cast<const float4*>(bp + 2 * cl);
        const float bx = bb.x + bb.y;
        const float by = bb.z + bb.w;
        const int col = nbase + cl;
        float2 v0 = make_float2(acc[nj][0] + bx, acc[nj][1] + by);
        float2 v1 = make_float2(acc[nj][2] + bx, acc[nj][3] + by);
        *reinterpret_cast<float2*>(out + (size_t)r0 * DIM + col)       = v0;
        *reinterpret_cast<float2*>(out + (size_t)(r0 + 8) * DIM + col) = v1;
    }
}

// ---------------- launch: ONE kernel ----------------
extern "C" void kernel_launch(void* const* d_in, const int* in_sizes, int n_in,
                              void* d_out, int out_size) {
    const float* x     = (const float*)d_in[0];   // [8192, 128] fp32
    const float* coeff = (const float*)d_in[1];   // [16384, 4]  fp32
    float* out = (float*)d_out;                   // [8192, 128] fp32

    cudaFuncSetAttribute(kan_fused, cudaFuncAttributeMaxDynamicSharedMemorySize,
                         SMEM_TOTAL);
    kan_fused<<<NCTA, THREADS, SMEM_TOTAL>>>(x, coeff, out);
}

// round 16
// speedup vs baseline: 1.2149x; 1.1910x over previous
#include <cuda_runtime.h>
#include <cuda_fp16.h>
#include <cstdint>

// Problem dims
#define BATCH    8192
#define DIM      128          // in_dim == out_dim
#define KTOT     384          // permuted K: k = (half*3+pw)*64 + (j&63)
#define MTILE    64           // batch rows per CTA
#define THREADS  512          // 16 warps: 4 (m) x 4 (n)
#define NCTA     (BATCH / MTILE)   // 128 = one full wave

// fp16 coefficients (permuted K order): g_Bf[o*384 + c*64 + (j&63)]
__device__ __half g_Bf[DIM * KTOT];
__device__ float g_Bias[DIM];

// smem layout (144 KB, all resident):
//   A: 6 chunks x Af[64][64]f16 8K @ c*8192           = 48 KB @ 0
//   B: 6 chunks x Bf[128][64]f16 16K @ 49152 + c*16384 = 96 KB
#define A_CHUNK_STRIDE 8192u
#define B_BASE         49152u
#define B_CHUNK_STRIDE 16384u
#define SMEM_TOTAL     147456

// ---------------- helpers ----------------
__device__ __forceinline__ uint32_t smem_u32(const void* p) {
    uint32_t a;
    asm("{ .reg .u64 t; cvta.to.shared.u64 t, %1; cvt.u32.u64 %0, t; }" : "=r"(a) : "l"(p));
    return a;
}
__device__ __forceinline__ uint32_t swz128(uint32_t off) { return off ^ ((off >> 3) & 0x70); }

#define CP_ASYNC16(dst_u32, src_ptr)                                              \
    asm volatile("{ .reg .u64 g; cvta.to.global.u64 g, %1;\n"                     \
                 "cp.async.cg.shared.global [%0], [g], 16; }"                     \
                 :: "r"(dst_u32), "l"(src_ptr) : "memory")
#define CP_COMMIT()  asm volatile("cp.async.commit_group;" ::: "memory")
#define CP_WAITG(n)  asm volatile("cp.async.wait_group %0;" :: "n"(n) : "memory")

#define LDSM4(r, addr)                                                            \
    asm volatile("ldmatrix.sync.aligned.m8n8.x4.shared.b16 {%0,%1,%2,%3}, [%4];"  \
                 : "=r"((r)[0]), "=r"((r)[1]), "=r"((r)[2]), "=r"((r)[3])         \
                 : "r"(addr))

#define MMA_F16(c, A, b0v, b1v)                                                   \
    asm volatile("mma.sync.aligned.m16n8k16.row.col.f32.f16.f16.f32 "             \
                 "{%0,%1,%2,%3}, {%4,%5,%6,%7}, {%8,%9}, {%0,%1,%2,%3};"          \
                 : "+f"((c)[0]), "+f"((c)[1]), "+f"((c)[2]), "+f"((c)[3])         \
                 : "r"((A)[0]), "r"((A)[1]), "r"((A)[2]), "r"((A)[3]),            \
                   "r"(b0v), "r"(b1v))

__device__ __forceinline__ uint32_t pack_half2(float a, float b) {
    __half2 h = __floats2half2_rn(a, b);
    return *reinterpret_cast<uint32_t*>(&h);
}

// ---------------- prep: coeff -> fp16 (permuted K), vectorized, + bias ----------------
// One thread per edge-PAIR (o, 2jp..2jp+1). 8192 pairs over 32 CTAs x 256 thr.
// LDG: 2 consecutive float4 (32 B/thread, fully coalesced).
// STG: 3 x st.b32 (packed half2) instead of 6 scattered st.b16.
__global__ void prep_kernel(const float* __restrict__ coeff) {
    asm volatile("griddepcontrol.launch_dependents;");

    const int tid = threadIdx.x;
    const int idx = blockIdx.x * 256 + tid;       // pair index [0, 8192)
    const int o  = idx >> 6;                      // 4 o's per block
    const int jp = idx & 63;                      // pair 0..63 -> j = 2*jp
    const float4* cp = reinterpret_cast<const float4*>(coeff) + 2 * (size_t)idx;
    float4 c0 = cp[0];
    float4 c1 = cp[1];
    const int cbase = (jp >= 32) ? 3 : 0;
    const int joff  = (2 * jp) & 63;
    uint32_t* dst = reinterpret_cast<uint32_t*>(g_Bf + o * KTOT + joff);
    dst[(cbase + 0) * 32] = pack_half2(c0.y, c1.y);
    dst[(cbase + 1) * 32] = pack_half2(c0.z, c1.z);
    dst[(cbase + 2) * 32] = pack_half2(c0.w, c1.w);

    // bias: warp w covers one (o, half); reduce and combine via smem
    float s = c0.x + c1.x;
#pragma unroll
    for (int off = 16; off; off >>= 1)
        s += __shfl_xor_sync(0xffffffffu, s, off);
    __shared__ float ps[8];
    if ((tid & 31) == 0) ps[tid >> 5] = s;
    __syncthreads();
    if (tid < 4)
        g_Bias[blockIdx.x * 4 + tid] = ps[2 * tid] + ps[2 * tid + 1];
}

// ---------------- main kernel ----------------
__global__ void __launch_bounds__(THREADS, 1)
kan_mma(const float* __restrict__ x, float* __restrict__ out) {
    extern __shared__ char smem[];
    const uint32_t sb = smem_u32(smem);
    const int tid  = threadIdx.x;
    const int lane = tid & 31;
    const int wid  = tid >> 5;
    const int b0   = blockIdx.x * MTILE;

    // warp tile (16 x 32): 4 m-warps x 4 n-warps
    const int m0 = (wid & 3) * 16;
    const int n0 = (wid >> 2) * 32;

    // ---- 1) issue x loads FIRST (DRAM latency pole, prep-independent) ----
    const int sr = tid >> 3;                      // 0..63
    const int sq = tid & 7;                       // 0..7
    const float4* xr = reinterpret_cast<const float4*>(x + (size_t)(b0 + sr) * DIM);
    float4 xv0 = xr[sq * 2];
    float4 xv1 = xr[sq * 2 + 1];
    float4 xv2 = xr[16 + sq * 2];
    float4 xv3 = xr[16 + sq * 2 + 1];

    // ---- 2) wait for prep (g_Bf / g_Bias visible) ----
    asm volatile("griddepcontrol.wait;" ::: "memory");

    // ---- 3) issue ALL B cp.async immediately (two commit groups) ----
#pragma unroll
    for (int i = 0; i < 6; ++i) {
        int idx = tid + i * THREADS;              // chunks 0..2
        int cn = idx >> 10;
        int n = (idx >> 3) & 127, k8 = idx & 7;
        const __half* src = g_Bf + (size_t)n * KTOT + cn * 64 + k8 * 8;
        uint32_t dst = B_BASE + (uint32_t)cn * B_CHUNK_STRIDE
                     + swz128((uint32_t)(n * 128 + k8 * 16));
        CP_ASYNC16(sb + dst, src);
    }
    CP_COMMIT();
#pragma unroll
    for (int i = 6; i < 12; ++i) {
        int idx = tid + i * THREADS;              // chunks 3..5
        int cn = idx >> 10;
        int n = (idx >> 3) & 127, k8 = idx & 7;
        const __half* src = g_Bf + (size_t)n * KTOT + cn * 64 + k8 * 8;
        uint32_t dst = B_BASE + (uint32_t)cn * B_CHUNK_STRIDE
                     + swz128((uint32_t)(n * 128 + k8 * 16));
        CP_ASYNC16(sb + dst, src);
    }
    CP_COMMIT();

    // bias prefetch (overlaps with B flight)
    float2 bs[4];
#pragma unroll
    for (int nj = 0; nj < 4; ++nj)
        bs[nj] = *reinterpret_cast<const float2*>(g_Bias + n0 + nj * 8 + 2 * (lane & 3));

    // ---- 4) build A tile WHILE B is in flight ----
    {
        const uint32_t abase = swz128((uint32_t)(sr * 128 + sq * 16));
#pragma unroll
        for (int h = 0; h < 2; ++h) {
            float xb[8], w[8];
            {
                float4 v0 = h ? xv2 : xv0;
                float4 v1 = h ? xv3 : xv1;
                xb[0] = v0.x; xb[1] = v0.y; xb[2] = v0.z; xb[3] = v0.w;
                xb[4] = v1.x; xb[5] = v1.y; xb[6] = v1.z; xb[7] = v1.w;
            }
#pragma unroll
            for (int i = 0; i < 8; ++i) w[i] = xb[i];
#pragma unroll
            for (int pw = 0; pw < 3; ++pw) {
                uint4 pk = make_uint4(pack_half2(w[0], w[1]), pack_half2(w[2], w[3]),
                                      pack_half2(w[4], w[5]), pack_half2(w[6], w[7]));
                *reinterpret_cast<uint4*>(
                    smem + (uint32_t)(h * 3 + pw) * A_CHUNK_STRIDE + abase) = pk;
                if (pw < 2) {
#pragma unroll
                    for (int i = 0; i < 8; ++i) w[i] *= xb[i];
                }
            }
        }
    }

    // ---- 5) mainloop: phase0 after half of B, phase1 after all ----
    float acc[4][4];
#pragma unroll
    for (int nj = 0; nj < 4; ++nj)
#pragma unroll
        for (int i = 0; i < 4; ++i) acc[nj][i] = 0.f;

    const uint32_t a_row = (uint32_t)(m0 + (lane & 15));
    const uint32_t a_kb  = (uint32_t)((lane >> 4) * 16);
    const uint32_t b_row = (uint32_t)(n0 + (lane & 7) + ((lane >> 4) << 3));
    const uint32_t b_kb  = (uint32_t)(((lane >> 3) & 1) * 16);

    uint32_t af[3][4], bf[3][2][4];

    auto load_step = [&](int step, int s) {
        const uint32_t ab = (uint32_t)(step >> 2) * A_CHUNK_STRIDE;
        const uint32_t bb = B_BASE + (uint32_t)(step >> 2) * B_CHUNK_STRIDE;
        const int ks = step & 3;
        LDSM4(af[s], sb + ab + swz128(a_row * 128 + ks * 32 + a_kb));
#pragma unroll
        for (int ni = 0; ni < 2; ++ni) {
            uint32_t off = swz128((b_row + ni * 16) * 128 + ks * 32 + b_kb);
            LDSM4(bf[s][ni], sb + bb + off);
        }
    };
    auto mma_step = [&](int s) {
#pragma unroll
        for (int nj = 0; nj < 4; ++nj) {
            const int ni = nj >> 1, br = (nj & 1) * 2;
            MMA_F16(acc[nj], af[s], bf[s][ni][br], bf[s][ni][br + 1]);
        }
    };

    // phase 0: chunks 0-2 (steps 0..11)
    CP_WAITG(1);
    __syncthreads();
    load_step(0, 0);
    load_step(1, 1);
#pragma unroll
    for (int s = 0; s < 12; ++s) {
        if (s + 2 < 12) load_step(s + 2, (s + 2) % 3);
        mma_step(s % 3);
    }

    // phase 1: chunks 3-5 (steps 12..23)
    CP_WAITG(0);
    __syncthreads();
    load_step(12, 0);
    load_step(13, 1);
#pragma unroll
    for (int s = 0; s < 12; ++s) {
        if (s + 2 < 12) load_step(12 + s + 2, (s + 2) % 3);
        mma_step(s % 3);
    }

    // ---- 6) epilogue: bias + store ----
    const int r0 = b0 + m0 + (lane >> 2);
#pragma unroll
    for (int nj = 0; nj < 4; ++nj) {
        const int col = n0 + nj * 8 + 2 * (lane & 3);
        float2 v0 = make_float2(acc[nj][0] + bs[nj].x, acc[nj][1] + bs[nj].y);
        float2 v1 = make_float2(acc[nj][2] + bs[nj].x, acc[nj][3] + bs[nj].y);
        *reinterpret_cast<float2*>(out + (size_t)r0 * DIM + col)       = v0;
        *reinterpret_cast<float2*>(out + (size_t)(r0 + 8) * DIM + col) = v1;
    }
}

// ---------------- launch ----------------
extern "C" void kernel_launch(void* const* d_in, const int* in_sizes, int n_in,
                              void* d_out, int out_size) {
    const float* x     = (const float*)d_in[0];   // [8192, 128] fp32
    const float* coeff = (const float*)d_in[1];   // [16384, 4]  fp32
    float* out = (float*)d_out;                   // [8192, 128] fp32

    cudaFuncSetAttribute(kan_mma, cudaFuncAttributeMaxDynamicSharedMemorySize, SMEM_TOTAL);

    prep_kernel<<<32, 256>>>(coeff);

    // PDL: main may start while prep runs; griddepcontrol.wait orders g_Bf reads.
    cudaLaunchConfig_t cfg = {};
    cfg.gridDim  = dim3(NCTA, 1, 1);
    cfg.blockDim = dim3(THREADS, 1, 1);
    cfg.dynamicSmemBytes = SMEM_TOTAL;
    cfg.stream = 0;
    cudaLaunchAttribute attr[1];
    attr[0].id = cudaLaunchAttributeProgrammaticStreamSerialization;
    attr[0].val.programmaticStreamSerializationAllowed = 1;
    cfg.attrs = attr;
    cfg.numAttrs = 1;
    cudaLaunchKernelEx(&cfg, kan_mma, x, out);
}